// round 4
// baseline (speedup 1.0000x reference)
#include <cuda_runtime.h>

// IF neuron multi-step scan, hard reset:
//   h_t = x_t + v_{t-1};  s_t = (h_t >= 1) ? 1 : 0;  v_t = s_t ? 0 : h_t
//
// R4: one thread per float4 lane, batch-4 SINGLE-buffered bursts
// (4x LDG.128 back-to-back, then 4x compute+STG.128), with
// __launch_bounds__(256, 7) to cap regs at 36 so all 1024 blocks are
// resident in ONE wave (the R3 version at 56 regs split into 1.73 waves).

__device__ __forceinline__ float4 if_step(float4 xv, float4& v)
{
    float h0 = xv.x + v.x;
    float h1 = xv.y + v.y;
    float h2 = xv.z + v.z;
    float h3 = xv.w + v.w;

    float4 s;
    s.x = (h0 >= 1.0f) ? 1.0f : 0.0f;
    s.y = (h1 >= 1.0f) ? 1.0f : 0.0f;
    s.z = (h2 >= 1.0f) ? 1.0f : 0.0f;
    s.w = (h3 >= 1.0f) ? 1.0f : 0.0f;

    v.x = (h0 >= 1.0f) ? 0.0f : h0;
    v.y = (h1 >= 1.0f) ? 0.0f : h1;
    v.z = (h2 >= 1.0f) ? 0.0f : h2;
    v.w = (h3 >= 1.0f) ? 0.0f : h3;
    return s;
}

// T must be a multiple of 4 (T=32 here).
__global__ __launch_bounds__(256, 7) void if_scan_sb4(
    const float4* __restrict__ x,   // [T, n4]
    const float4* __restrict__ v0,  // [n4]
    float4* __restrict__ out,       // [T, n4]
    int n4, int T)
{
    int i = blockIdx.x * blockDim.x + threadIdx.x;
    if (i >= n4) return;

    float4 v = v0[i];
    const float4* xp = x + i;
    float4* op = out + i;

    for (int t = 0; t < T; t += 4) {
        // read burst: 4 independent LDG.128
        float4 b0 = __ldcs(xp);
        float4 b1 = __ldcs(xp + n4);
        float4 b2 = __ldcs(xp + 2 * n4);
        float4 b3 = __ldcs(xp + 3 * n4);
        xp += 4 * n4;

        // compute + write burst: 4 STG.128
        float4 s0 = if_step(b0, v);
        float4 s1 = if_step(b1, v);
        float4 s2 = if_step(b2, v);
        float4 s3 = if_step(b3, v);

        __stcs(op, s0);
        __stcs(op + n4, s1);
        __stcs(op + 2 * n4, s2);
        __stcs(op + 3 * n4, s3);
        op += 4 * n4;
    }
}

// Generic fallback for T not divisible by 4 (not hit for this shape).
__global__ __launch_bounds__(256) void if_scan_plain(
    const float4* __restrict__ x,
    const float4* __restrict__ v0,
    float4* __restrict__ out,
    int n4, int T)
{
    int i = blockIdx.x * blockDim.x + threadIdx.x;
    if (i >= n4) return;

    float4 v = v0[i];
    const float4* xp = x + i;
    float4* op = out + i;

    for (int t = 0; t < T; ++t) {
        float4 xv = __ldcs(xp); xp += n4;
        float4 s = if_step(xv, v);
        __stcs(op, s); op += n4;
    }
}

extern "C" void kernel_launch(void* const* d_in, const int* in_sizes, int n_in,
                              void* d_out, int out_size)
{
    const float* x_seq  = (const float*)d_in[0];   // [T, B, D]
    const float* v_init = (const float*)d_in[1];   // [B, D]

    int N = in_sizes[1];              // B * D
    int T = in_sizes[0] / N;          // timesteps
    int n4 = N / 4;

    int block = 256;
    int grid = (n4 + block - 1) / block;

    if ((T & 3) == 0) {
        if_scan_sb4<<<grid, block>>>(
            (const float4*)x_seq, (const float4*)v_init,
            (float4*)d_out, n4, T);
    } else {
        if_scan_plain<<<grid, block>>>(
            (const float4*)x_seq, (const float4*)v_init,
            (float4*)d_out, n4, T);
    }
}